// round 6
// baseline (speedup 1.0000x reference)
#include <cuda_runtime.h>
#include <cuda_bf16.h>
#include <cstdint>

#define B_   8
#define C_   256
#define H_   96
#define W_   96
#define HW_  (H_*W_)          // 9216
#define G_   4
#define CG_  64
#define HO_  192
#define WO_  192
#define HOWO_ (HO_*WO_)
#define NOUT_ 32

// Scratch coords (ix, iy) per output pixel, layout [n][oy][ox]
__device__ __align__(16) float2 g_coords[B_ * G_ * HO_ * WO_];   // 9.4 MB

// ---------------------------------------------------------------------------
// Kernel 1: offset head GEMV. 256 threads, 1 px/thread, grid 288 (~2 waves).
// Weights broadcast from SMEM as float4; x loads double-buffered in regs.
// ---------------------------------------------------------------------------
__global__ __launch_bounds__(256) void dysample_offset_kernel(
    const float* __restrict__ x,
    const float* __restrict__ w_off,
    const float* __restrict__ b_off)
{
    __shared__ __align__(16) float4 w_sh4[NOUT_ * C_ / 4];   // 32 KB
    __shared__ float b_sh[NOUT_];

    const int tid = threadIdx.x;
#pragma unroll
    for (int i = 0; i < 8; i++)
        w_sh4[tid + i * 256] = ((const float4*)w_off)[tid + i * 256];
    if (tid < NOUT_) b_sh[tid] = b_off[tid];
    __syncthreads();

    const int base = blockIdx.x * 256;        // 9216 % 256 == 0 -> single b
    const int b    = base / HW_;
    const int p    = base % HW_ + tid;

    const float* xp = x + (size_t)b * C_ * HW_ + p;

    float acc[NOUT_];
#pragma unroll
    for (int o = 0; o < NOUT_; o++) acc[o] = 0.f;

    float c0 = xp[0], c1 = xp[HW_], c2 = xp[2 * HW_], c3 = xp[3 * HW_];

#pragma unroll 1
    for (int cb = 0; cb < C_; cb += 4) {
        const int cn = (cb + 4 < C_) ? (cb + 4) : (C_ - 4);
        const float n0 = xp[(cn + 0) * HW_];
        const float n1 = xp[(cn + 1) * HW_];
        const float n2 = xp[(cn + 2) * HW_];
        const float n3 = xp[(cn + 3) * HW_];
#pragma unroll
        for (int o = 0; o < NOUT_; o++) {
            const float4 wv = w_sh4[o * (C_ / 4) + (cb >> 2)];
            float t = acc[o];
            t = fmaf(c0, wv.x, t);
            t = fmaf(c1, wv.y, t);
            t = fmaf(c2, wv.z, t);
            t = fmaf(c3, wv.w, t);
            acc[o] = t;
        }
        c0 = n0; c1 = n1; c2 = n2; c3 = n3;
    }

    const int h = p / W_;
    const int w = p % W_;
    const float wf = (float)w, hf = (float)h;
#pragma unroll
    for (int gi = 0; gi < G_; gi++) {
#pragma unroll
        for (int sy = 0; sy < 2; sy++) {
#pragma unroll
            for (int sx = 0; sx < 2; sx++) {
                const int idx = gi * 4 + sy * 2 + sx;
                float ix = wf + (acc[idx]      + b_sh[idx])      * 0.25f;
                float iy = hf + (acc[16 + idx] + b_sh[16 + idx]) * 0.25f;
                ix = fminf(fmaxf(ix, 0.f), (float)(W_ - 1));
                iy = fminf(fmaxf(iy, 0.f), (float)(H_ - 1));
                const int n  = b * G_ + gi;
                const int oy = 2 * h + sy;
                const int ox = 2 * w + sx;
                g_coords[((size_t)n * HO_ + oy) * WO_ + ox] = make_float2(ix, iy);
            }
        }
    }
}

// ---------------------------------------------------------------------------
// Kernel 2: bilinear gather, channel-interleaved float4 tile.
// Block = (n, 4 output rows x 192 cols), 256 threads, 3 px/thread.
// Tile: [TR rows][96 cols] float4 cells = 4 consecutive channels per cell.
// Each tap = 1 LDS.128 (serves 4 channels); adjacent px broadcast-merge.
// ---------------------------------------------------------------------------
#define TR    4
#define TST4  97     // float4 stride per tile row

__global__ __launch_bounds__(256) void dysample_sample_kernel(
    const float* __restrict__ x,
    float* __restrict__ out)
{
    __shared__ __align__(16) float4 tile[TR * TST4];   // 6.2 KB

    const int tid = threadIdx.x;
    const int n   = blockIdx.y;
    const int b   = n >> 2;
    const int gi  = n & 3;
    const int oy0 = blockIdx.x * 4;

    int r0 = (oy0 >> 1) - 1;
    if (r0 < 0) r0 = 0;
    if (r0 > H_ - TR) r0 = H_ - TR;          // 92
    const int r1 = r0 + TR - 1;

    // Per-pixel state: weights + 4 tap indices (tile or global) + output base
    float4 wts[3];
    int t00[3], t01[3], t10[3], t11[3];
    int obase[3];
    unsigned fbmask = 0;

#pragma unroll
    for (int k = 0; k < 3; k++) {
        const int p   = tid + k * 256;       // 0..767
        const int oyr = p / WO_;
        const int ox  = p % WO_;
        const float2 c = g_coords[((size_t)n * HO_ + oy0 + oyr) * WO_ + ox];
        const float x0f = floorf(c.x), y0f = floorf(c.y);
        const int xi0 = (int)x0f, yi0 = (int)y0f;
        const float wx = c.x - x0f, wy = c.y - y0f;
        const int xi1 = min(xi0 + 1, W_ - 1);
        const int yi1 = min(yi0 + 1, H_ - 1);
        wts[k] = make_float4((1.f - wy) * (1.f - wx), (1.f - wy) * wx,
                             wy * (1.f - wx),         wy * wx);
        if (yi0 >= r0 && yi1 <= r1) {
            t00[k] = (yi0 - r0) * TST4 + xi0;
            t01[k] = (yi0 - r0) * TST4 + xi1;
            t10[k] = (yi1 - r0) * TST4 + xi0;
            t11[k] = (yi1 - r0) * TST4 + xi1;
        } else {
            fbmask |= 1u << k;
            t00[k] = yi0 * W_ + xi0;
            t01[k] = yi0 * W_ + xi1;
            t10[k] = yi1 * W_ + xi0;
            t11[k] = yi1 * W_ + xi1;
        }
        obase[k] = (oy0 + oyr) * WO_ + ox;
    }

    const int ch0 = b * C_ + gi * CG_;
    const float* xg = x + (size_t)ch0 * HW_;
    float* og = out + (size_t)ch0 * HOWO_;

#pragma unroll 1
    for (int cb = 0; cb < CG_; cb += 4) {
        const float* xc = xg + (size_t)cb * HW_;
        __syncthreads();                      // previous chunk reads done
        // Fill: TR*96 = 384 cells, 256 threads
        {
            int i = tid;
            {
                const int r = i / 96, c = i % 96;
                const float* s = xc + (r0 + r) * W_ + c;
                tile[r * TST4 + c] = make_float4(s[0], s[HW_], s[2 * HW_], s[3 * HW_]);
            }
            i += 256;
            if (i < TR * 96) {
                const int r = i / 96, c = i % 96;
                const float* s = xc + (r0 + r) * W_ + c;
                tile[r * TST4 + c] = make_float4(s[0], s[HW_], s[2 * HW_], s[3 * HW_]);
            }
        }
        __syncthreads();

#pragma unroll
        for (int k = 0; k < 3; k++) {
            const float4 wv = wts[k];
            float* op = og + (size_t)cb * HOWO_ + obase[k];
            if (!((fbmask >> k) & 1u)) {
                const float4 v00 = tile[t00[k]];
                const float4 v01 = tile[t01[k]];
                const float4 v10 = tile[t10[k]];
                const float4 v11 = tile[t11[k]];
                float r0v = wv.x * v00.x;
                float r1v = wv.x * v00.y;
                float r2v = wv.x * v00.z;
                float r3v = wv.x * v00.w;
                r0v = fmaf(wv.y, v01.x, r0v);
                r1v = fmaf(wv.y, v01.y, r1v);
                r2v = fmaf(wv.y, v01.z, r2v);
                r3v = fmaf(wv.y, v01.w, r3v);
                r0v = fmaf(wv.z, v10.x, r0v);
                r1v = fmaf(wv.z, v10.y, r1v);
                r2v = fmaf(wv.z, v10.z, r2v);
                r3v = fmaf(wv.z, v10.w, r3v);
                r0v = fmaf(wv.w, v11.x, r0v);
                r1v = fmaf(wv.w, v11.y, r1v);
                r2v = fmaf(wv.w, v11.z, r2v);
                r3v = fmaf(wv.w, v11.w, r3v);
                op[0]               = r0v;
                op[(size_t)HOWO_]   = r1v;
                op[(size_t)2*HOWO_] = r2v;
                op[(size_t)3*HOWO_] = r3v;
            } else {
#pragma unroll
                for (int ch = 0; ch < 4; ch++) {
                    const float* gc = xc + (size_t)ch * HW_;
                    float v = wv.x * __ldg(gc + t00[k]);
                    v = fmaf(wv.y, __ldg(gc + t01[k]), v);
                    v = fmaf(wv.z, __ldg(gc + t10[k]), v);
                    v = fmaf(wv.w, __ldg(gc + t11[k]), v);
                    op[(size_t)ch * HOWO_] = v;
                }
            }
        }
    }
}

// ---------------------------------------------------------------------------
extern "C" void kernel_launch(void* const* d_in, const int* in_sizes, int n_in,
                              void* d_out, int out_size)
{
    const float* x     = (const float*)d_in[0];
    const float* w_off = (const float*)d_in[1];
    const float* b_off = (const float*)d_in[2];
    float* out = (float*)d_out;

    dysample_offset_kernel<<<B_ * HW_ / 256, 256>>>(x, w_off, b_off);
    dysample_sample_kernel<<<dim3(48, B_ * G_), dim3(256)>>>(x, out);
}

// round 7
// speedup vs baseline: 1.1786x; 1.1786x over previous
#include <cuda_runtime.h>
#include <cuda_bf16.h>
#include <cstdint>

#define B_   8
#define C_   256
#define H_   96
#define W_   96
#define HW_  (H_*W_)          // 9216
#define G_   4
#define CG_  64
#define HO_  192
#define WO_  192
#define HOWO_ (HO_*WO_)
#define NOUT_ 32

// Scratch coords (ix, iy) per output pixel, layout [n][oy][ox] (linear pid)
__device__ __align__(16) float2 g_coords[B_ * G_ * HO_ * WO_];   // 9.4 MB

// ---------------------------------------------------------------------------
// Kernel 1: offset head GEMV (R1 shape: 192 thr = 96x2, grid 48x8).
// ---------------------------------------------------------------------------
__global__ __launch_bounds__(192) void dysample_offset_kernel(
    const float* __restrict__ x,
    const float* __restrict__ w_off,
    const float* __restrict__ b_off)
{
    __shared__ __align__(16) float w_sh[NOUT_ * C_];   // 32 KB, natural [o][c]
    __shared__ float b_sh[NOUT_];

    const int tid = threadIdx.y * 96 + threadIdx.x;
    for (int i = tid; i < NOUT_ * C_; i += 192) w_sh[i] = w_off[i];
    if (tid < NOUT_) b_sh[tid] = b_off[tid];
    __syncthreads();

    const int b = blockIdx.y;
    const int h = blockIdx.x * 2 + threadIdx.y;
    const int w = threadIdx.x;

    const float* xp = x + (size_t)b * C_ * HW_ + h * W_ + w;

    float acc[NOUT_];
#pragma unroll
    for (int o = 0; o < NOUT_; o++) acc[o] = 0.f;

#pragma unroll 2
    for (int cb = 0; cb < C_; cb += 4) {
        const float xv0 = xp[(cb + 0) * HW_];
        const float xv1 = xp[(cb + 1) * HW_];
        const float xv2 = xp[(cb + 2) * HW_];
        const float xv3 = xp[(cb + 3) * HW_];
#pragma unroll
        for (int o = 0; o < NOUT_; o++) {
            const float4 wv = *(const float4*)&w_sh[o * C_ + cb];
            float t = acc[o];
            t = fmaf(xv0, wv.x, t);
            t = fmaf(xv1, wv.y, t);
            t = fmaf(xv2, wv.z, t);
            t = fmaf(xv3, wv.w, t);
            acc[o] = t;
        }
    }

    const float wf = (float)w;
    const float hf = (float)h;
#pragma unroll
    for (int gi = 0; gi < G_; gi++) {
#pragma unroll
        for (int sy = 0; sy < 2; sy++) {
#pragma unroll
            for (int sx = 0; sx < 2; sx++) {
                const int idx = gi * 4 + sy * 2 + sx;
                float ix = wf + (acc[idx]      + b_sh[idx])      * 0.25f;
                float iy = hf + (acc[16 + idx] + b_sh[16 + idx]) * 0.25f;
                ix = fminf(fmaxf(ix, 0.f), (float)(W_ - 1));
                iy = fminf(fmaxf(iy, 0.f), (float)(H_ - 1));
                const int n  = b * G_ + gi;
                const int oy = 2 * h + sy;
                const int ox = 2 * w + sx;
                g_coords[((size_t)n * HO_ + oy) * WO_ + ox] = make_float2(ix, iy);
            }
        }
    }
}

// ---------------------------------------------------------------------------
// Kernel 2: direct bilinear gather, pointer+immediate addressing.
// One thread per output pixel; 4 precomputed tap pointers; 64 channels as
// outer-8 x inner-8 (all inner addresses are SASS immediate offsets).
// No SMEM, no barriers, no divergence.
// ---------------------------------------------------------------------------
__global__ __launch_bounds__(256, 4) void dysample_sample_kernel(
    const float* __restrict__ x,
    float* __restrict__ out)
{
    const int pid = blockIdx.x * 256 + threadIdx.x;   // 0 .. 1179647
    const int n   = pid / HOWO_;
    const int rem = pid % HOWO_;
    const int b   = n >> 2;
    const int gi  = n & 3;

    const float2 c = g_coords[pid];
    const float x0f = floorf(c.x), y0f = floorf(c.y);
    const int xi0 = (int)x0f, yi0 = (int)y0f;
    const float wx = c.x - x0f, wy = c.y - y0f;
    const int xi1 = min(xi0 + 1, W_ - 1);
    const int yi1 = min(yi0 + 1, H_ - 1);

    const float w00 = (1.f - wy) * (1.f - wx);
    const float w01 = (1.f - wy) * wx;
    const float w10 = wy * (1.f - wx);
    const float w11 = wy * wx;

    const float* __restrict__ base = x + (size_t)(b * C_ + gi * CG_) * HW_;
    const float* __restrict__ p00 = base + yi0 * W_ + xi0;
    const float* __restrict__ p01 = base + yi0 * W_ + xi1;
    const float* __restrict__ p10 = base + yi1 * W_ + xi0;
    const float* __restrict__ p11 = base + yi1 * W_ + xi1;
    float* __restrict__ op = out + (size_t)(b * C_ + gi * CG_) * HOWO_ + rem;

#pragma unroll 1
    for (int cb = 0; cb < CG_; cb += 8) {
        const float* q00 = p00 + cb * HW_;
        const float* q01 = p01 + cb * HW_;
        const float* q10 = p10 + cb * HW_;
        const float* q11 = p11 + cb * HW_;
        float* oq = op + (size_t)cb * HOWO_;
#pragma unroll
        for (int cc = 0; cc < 8; cc++) {
            float v = w00 * __ldg(q00 + cc * HW_);
            v = fmaf(w01, __ldg(q01 + cc * HW_), v);
            v = fmaf(w10, __ldg(q10 + cc * HW_), v);
            v = fmaf(w11, __ldg(q11 + cc * HW_), v);
            oq[(size_t)cc * HOWO_] = v;
        }
    }
}

// ---------------------------------------------------------------------------
extern "C" void kernel_launch(void* const* d_in, const int* in_sizes, int n_in,
                              void* d_out, int out_size)
{
    const float* x     = (const float*)d_in[0];
    const float* w_off = (const float*)d_in[1];
    const float* b_off = (const float*)d_in[2];
    float* out = (float*)d_out;

    dysample_offset_kernel<<<dim3(48, B_), dim3(96, 2)>>>(x, w_off, b_off);
    dysample_sample_kernel<<<(B_ * G_ * HOWO_) / 256, 256>>>(x, out);
}